// round 13
// baseline (speedup 1.0000x reference)
#include <cuda_runtime.h>
#include <cuda_fp16.h>

// Problem constants (fixed by the dataset's reference_code)
#define HW_DIM     512
#define NB         6
#define NLOOPS     4
#define NDET       4096
#define NSAMP      128
#define NBATCH     4
#define NPTS       (NDET * NSAMP)          // 524288
#define PIX        (512 * 512)             // per-channel elements
#define B_STRIDE   (2 * NB * PIX)          // per-batch elements (12 channels)

// Pair-packed refinement, 8 B per (pixel, bucket-pair):
//   g_pairs[parity][b][j][pix] = uint2{ h2(x_ka,y_ka), h2(x_kb,y_kb) }
//   parity 0 (E): pairs (0,1),(2,3),(4,5)   ka = 2j, kb = 2j+1
//   parity 1 (O): pairs (1,2),(3,4),(5,0)   ka = 2j+1, kb = (2j+2)%6
// Taps (k0, k0+1 mod 6): parity = k0&1, j = k0>>1, slot0 = k0 always. 50 MB.
__device__ uint2 g_pairs[2 * NBATCH * 3 * PIX];

static __device__ __forceinline__ unsigned pack_h2(float a, float b)
{
    __half2 h = __floats2half2_rn(a, b);
    return *reinterpret_cast<unsigned*>(&h);
}

// ---------------------------------------------------------------------------
// Repack: read each source channel ONCE (50 MB), write each bucket's h2 word
// into its E-slot and O-slot (50 MB). 100 MB total, no smem, full occupancy.
// Thread <-> (b, k, 4 pixels). Stores are stride-2 4B words -> line-coalesced.
// ---------------------------------------------------------------------------
__global__ void __launch_bounds__(256)
repack_kernel(const float* __restrict__ refinement)
{
    const int t = blockIdx.x * blockDim.x + threadIdx.x;
    const int quad  = t % (PIX / 4);
    const int slice = t / (PIX / 4);        // b*NB + k
    const int p     = quad * 4;

    const int b = slice / NB;
    const int k = slice - b * NB;

    const float* ch0 = refinement + (long)b * B_STRIDE + (long)(2 * k)     * PIX;
    const float* ch1 = refinement + (long)b * B_STRIDE + (long)(2 * k + 1) * PIX;

    const float4 xv = *reinterpret_cast<const float4*>(ch0 + p);
    const float4 yv = *reinterpret_cast<const float4*>(ch1 + p);

    unsigned w[4];
    w[0] = pack_h2(xv.x, yv.x);
    w[1] = pack_h2(xv.y, yv.y);
    w[2] = pack_h2(xv.z, yv.z);
    w[3] = pack_h2(xv.w, yv.w);

    // E volume: j = k>>1, slot = k&1
    // O volume: k odd -> j = k>>1, slot 0 ; k even -> j = ((k+5)%6)>>1, slot 1
    const int jE = k >> 1;
    const int sE = k & 1;
    const int jO = (k & 1) ? (k >> 1) : (((k + 5) % 6) >> 1);
    const int sO = 1 - (k & 1);

    unsigned* u = reinterpret_cast<unsigned*>(g_pairs);
    const long eBase = ((long)((0 * NBATCH + b) * 3 + jE) * PIX + p) * 2 + sE;
    const long oBase = ((long)((1 * NBATCH + b) * 3 + jO) * PIX + p) * 2 + sO;

    #pragma unroll
    for (int i = 0; i < 4; ++i) {
        u[eBase + 2 * i] = w[i];
        u[oBase + 2 * i] = w[i];
    }
}

// ---------------------------------------------------------------------------
// Refine: ONE aligned 8B gather per iteration, ILP=1 (proven best shape),
// exact fixed-point and 2-cycle early exits.
// ---------------------------------------------------------------------------
__global__ void __launch_bounds__(256)
refine_kernel(const float*  __restrict__ det_in,     // [NDET, NSAMP, 2]
              const float*  __restrict__ sampling,   // [NSAMP]
              const int*    __restrict__ bvec,       // [NDET]
              float*        __restrict__ out)        // [NDET, NSAMP, 2]
{
    const int t = blockIdx.x * blockDim.x + threadIdx.x;  // grid exact

    const int s = t & (NSAMP - 1);
    const int d = t >> 7;

    // Per-sample bucket setup — reference arithmetic exactly.
    const float base = sampling[s] * (float)NB;
    const float bif  = floorf(base);
    const int   bint = (int)bif;

    const float d0 = fabsf(bif - base);
    const float w0 = (d0 > 1.0f) ? 0.0f : (1.0f - d0);
    const float d1 = fabsf((bif + 1.0f) - base);
    const float w1 = (d1 > 1.0f) ? 0.0f : (1.0f - d1);

    const int k0     = bint % NB;
    const int parity = k0 & 1;
    const int j      = k0 >> 1;
    const uint2* __restrict__ ptr =
        g_pairs + (long)((parity * NBATCH + bvec[d]) * 3 + j) * PIX;

    const float2 det = reinterpret_cast<const float2*>(det_in)[t];
    float x = det.x, y = det.y;
    float px = x,  py = y;                   // det_{l-1}

    int prev1 = -1, prev2 = -1;
    #pragma unroll
    for (int l = 0; l < NLOOPS; ++l) {
        float xr = rintf(x);                 // round-half-even == jnp.round
        float yr = rintf(y);
        xr = fminf(fmaxf(xr, 0.0f), (float)(HW_DIM - 1));
        yr = fminf(fmaxf(yr, 0.0f), (float)(HW_DIM - 1));
        const int pix = (int)yr * HW_DIM + (int)xr;

        if (pix == prev1) break;             // fixed point: det unchanged
        if (pix == prev2) {                  // 2-cycle: alternates forever
            if ((NLOOPS - l) & 1) { x = px; y = py; }
            break;
        }
        prev2 = prev1;  prev1 = pix;
        px = x;  py = y;

        // ONE 8B gather: both taps' (x,y)
        const uint2 v = __ldg(ptr + pix);
        const float2 g0 = __half22float2(*reinterpret_cast<const __half2*>(&v.x));
        const float2 g1 = __half22float2(*reinterpret_cast<const __half2*>(&v.y));

        x = xr + (w0 * g0.x + w1 * g1.x);
        y = yr + (w0 * g0.y + w1 * g1.y);
    }

    reinterpret_cast<float2*>(out)[t] = make_float2(x, y);
}

extern "C" void kernel_launch(void* const* d_in, const int* in_sizes, int n_in,
                              void* d_out, int out_size)
{
    // Identify inputs by element count:
    //   det_indices : 1048576 f32, refinement : 12582912 f32,
    //   sampling : 128 f32, b : 4096 i32
    const float* det_in     = nullptr;
    const float* refinement = nullptr;
    const float* sampling   = nullptr;
    const int*   bvec       = nullptr;

    for (int i = 0; i < n_in; ++i) {
        switch (in_sizes[i]) {
            case 1048576:  det_in     = (const float*)d_in[i]; break;
            case 12582912: refinement = (const float*)d_in[i]; break;
            case 128:      sampling   = (const float*)d_in[i]; break;
            case 4096:     bvec       = (const int*)d_in[i];   break;
            default: break;
        }
    }

    {
        const int total = NBATCH * NB * (PIX / 4);     // 1572864 threads
        repack_kernel<<<total / 256, 256>>>(refinement);
    }
    refine_kernel<<<NPTS / 256, 256>>>(det_in, sampling, bvec, (float*)d_out);
}

// round 14
// speedup vs baseline: 3.1961x; 3.1961x over previous
#include <cuda_runtime.h>
#include <cuda_fp16.h>

// Problem constants (fixed by the dataset's reference_code)
#define HW_DIM     512
#define NB         6
#define NLOOPS     4
#define NDET       4096
#define NSAMP      128
#define NBATCH     4
#define NPTS       (NDET * NSAMP)          // 524288
#define PIX        (512 * 512)             // per-channel elements
#define B_STRIDE   (2 * NB * PIX)          // per-batch elements (12 channels)

// Pixel-major packed refinement: g_pix[b][pix][k] = half2(x,y), 25.2 MB.
// A pixel's 6 buckets are contiguous (24 B) -> both taps share an L1 line
// ~87% of the time; tap1's load is then an L1 hit, not a second L2 trip.
__device__ unsigned g_pix[(long)NBATCH * PIX * NB];

static __device__ __forceinline__ unsigned pack_h2(float a, float b)
{
    __half2 h = __floats2half2_rn(a, b);
    return *reinterpret_cast<unsigned*>(&h);
}

// ---------------------------------------------------------------------------
// Repack: [B,12,H,W] f32 -> [B,PIX,6] half2. 75 MB total traffic, fully
// coalesced both sides via a 6 KB smem transpose tile (256 pixels x 6 words).
// ---------------------------------------------------------------------------
__global__ void __launch_bounds__(256)
repack_kernel(const float* __restrict__ refinement)
{
    __shared__ unsigned sm[256 * NB];        // 6 KB, pixel-major [p][k]

    const int b    = blockIdx.x >> 10;       // PIX/256 = 1024 tiles per batch
    const int base = (blockIdx.x & 1023) * 256;
    const int tid  = threadIdx.x;

    const float* rb = refinement + (long)b * B_STRIDE + base + tid;

    // Phase 1: coalesced channel reads -> smem (stride-6 stores, 2-way bank)
    #pragma unroll
    for (int k = 0; k < NB; ++k) {
        const float xv = rb[(long)(2 * k)     * PIX];
        const float yv = rb[(long)(2 * k + 1) * PIX];
        sm[tid * NB + k] = pack_h2(xv, yv);
    }
    __syncthreads();

    // Phase 2: contiguous write-out, 3x uint2 per thread, fully coalesced
    uint2* dst = reinterpret_cast<uint2*>(g_pix + ((long)b * PIX + base) * NB);
    const uint2* src = reinterpret_cast<const uint2*>(sm);
    #pragma unroll
    for (int i = 0; i < 3; ++i)
        dst[tid + 256 * i] = src[tid + 256 * i];
}

// ---------------------------------------------------------------------------
// Refine: 2 LDGs per iteration hitting the SAME 24B pixel block (tap1 ~87%
// L1-hit). ILP=1 (proven best shape), exact fixed-point + 2-cycle exits.
// ---------------------------------------------------------------------------
__global__ void __launch_bounds__(256)
refine_kernel(const float*  __restrict__ det_in,     // [NDET, NSAMP, 2]
              const float*  __restrict__ sampling,   // [NSAMP]
              const int*    __restrict__ bvec,       // [NDET]
              float*        __restrict__ out)        // [NDET, NSAMP, 2]
{
    const int t = blockIdx.x * blockDim.x + threadIdx.x;  // grid exact

    const int s = t & (NSAMP - 1);
    const int d = t >> 7;

    // Per-sample bucket setup — reproduce reference arithmetic exactly.
    const float base = sampling[s] * (float)NB;
    const float bif  = floorf(base);
    const int   bint = (int)bif;

    const float d0 = fabsf(bif - base);
    const float w0 = (d0 > 1.0f) ? 0.0f : (1.0f - d0);
    const float d1 = fabsf((bif + 1.0f) - base);
    const float w1 = (d1 > 1.0f) ? 0.0f : (1.0f - d1);

    const int k0 = bint % NB;
    const int k1 = (bint + 1) % NB;
    const unsigned* __restrict__ up = g_pix + (long)bvec[d] * PIX * NB;

    const float2 det = reinterpret_cast<const float2*>(det_in)[t];
    float x = det.x, y = det.y;
    float px = x,  py = y;                   // det_{l-1}

    int prev1 = -1, prev2 = -1;
    #pragma unroll
    for (int l = 0; l < NLOOPS; ++l) {
        float xr = rintf(x);                 // round-half-even == jnp.round
        float yr = rintf(y);
        xr = fminf(fmaxf(xr, 0.0f), (float)(HW_DIM - 1));
        yr = fminf(fmaxf(yr, 0.0f), (float)(HW_DIM - 1));
        const int pix = (int)yr * HW_DIM + (int)xr;

        if (pix == prev1) break;             // fixed point: det unchanged
        if (pix == prev2) {                  // 2-cycle: alternates forever
            if ((NLOOPS - l) & 1) { x = px; y = py; }
            break;
        }
        prev2 = prev1;  prev1 = pix;
        px = x;  py = y;

        // Two 4B gathers into the SAME 24B pixel block
        const int o = pix * NB;
        const unsigned va = __ldg(up + o + k0);
        const unsigned vb = __ldg(up + o + k1);
        const float2 g0 = __half22float2(*reinterpret_cast<const __half2*>(&va));
        const float2 g1 = __half22float2(*reinterpret_cast<const __half2*>(&vb));

        x = xr + (w0 * g0.x + w1 * g1.x);
        y = yr + (w0 * g0.y + w1 * g1.y);
    }

    reinterpret_cast<float2*>(out)[t] = make_float2(x, y);
}

extern "C" void kernel_launch(void* const* d_in, const int* in_sizes, int n_in,
                              void* d_out, int out_size)
{
    // Identify inputs by element count:
    //   det_indices : 1048576 f32, refinement : 12582912 f32,
    //   sampling : 128 f32, b : 4096 i32
    const float* det_in     = nullptr;
    const float* refinement = nullptr;
    const float* sampling   = nullptr;
    const int*   bvec       = nullptr;

    for (int i = 0; i < n_in; ++i) {
        switch (in_sizes[i]) {
            case 1048576:  det_in     = (const float*)d_in[i]; break;
            case 12582912: refinement = (const float*)d_in[i]; break;
            case 128:      sampling   = (const float*)d_in[i]; break;
            case 4096:     bvec       = (const int*)d_in[i];   break;
            default: break;
        }
    }

    repack_kernel<<<NBATCH * (PIX / 256), 256>>>(refinement);   // 4096 blocks
    refine_kernel<<<NPTS / 256, 256>>>(det_in, sampling, bvec, (float*)d_out);
}